// round 6
// baseline (speedup 1.0000x reference)
#include <cuda_runtime.h>
#include <cstdint>

// Dendrite: out[b,d] = sum_{v=1..255} lin_w[v-1] * prod_{s: bit(7-s) of v} p_s + lin_b,
//   p_s = sigmoid(k*(w*x-q)).
// Multilinear Horner (255 FMA / output) evaluated in packed f32x2: each thread
// computes T=4 batch rows as two packed pairs. Weights stored as duplicated
// (w,w) 64-bit pairs in shared so every fma2 consumes them directly.

static constexpr int B = 8192;
static constexpr int D = 32;
static constexpr int S = 8;

using u64 = unsigned long long;

__device__ __forceinline__ u64 fma2(u64 a, u64 b, u64 c) {
    u64 d;
    asm("fma.rn.f32x2 %0, %1, %2, %3;" : "=l"(d) : "l"(a), "l"(b), "l"(c));
    return d;
}
__device__ __forceinline__ u64 pack2(float lo, float hi) {
    u64 d;
    asm("mov.b64 %0, {%1, %2};" : "=l"(d) : "f"(lo), "f"(hi));
    return d;
}
__device__ __forceinline__ void unpack2(u64 v, float& lo, float& hi) {
    asm("mov.b64 {%0, %1}, %2;" : "=f"(lo), "=f"(hi) : "l"(v));
}
__device__ __forceinline__ float fast_sigmoid_prehalved(float arg_half) {
    // sigmoid(a) = 0.5*tanh(a/2)+0.5 ; caller supplies a/2.
    float t;
    asm("tanh.approx.f32 %0, %1;" : "=f"(t) : "f"(arg_half));
    return fmaf(0.5f, t, 0.5f);
}

__global__ __launch_bounds__(128)
void dendrite_kernel(const float* __restrict__ x,      // [B, 1, S]
                     const float* __restrict__ k,      // [D, S]
                     const float* __restrict__ w,      // [D, S]
                     const float* __restrict__ q,      // [D, S]
                     const float* __restrict__ lin_w,  // [1, 255]
                     const float* __restrict__ lin_b,  // [1]
                     float* __restrict__ out)          // [B, 1, D] -> b*D + d
{
    __shared__ __align__(16) u64 sW2[256];   // (c[v], c[v]); c[0]=0
    __shared__ float sA[S][D];               // [s][d] = 0.5*k*w
    __shared__ float sC[S][D];               // [s][d] = -0.5*k*q

    const int tid = threadIdx.x;   // 128 threads
#pragma unroll
    for (int i = tid; i < 256; i += 128) {
        const float cv = (i == 0) ? 0.0f : lin_w[i - 1];
        sW2[i] = pack2(cv, cv);
        const int dd = i >> 3, ss = i & 7;   // i = d*8 + s matches flat [D,S]
        const float kh = 0.5f * k[i];
        sA[ss][dd] = kh * w[i];
        sC[ss][dd] = -kh * q[i];
    }
    __syncthreads();

    const int d = tid & 31;                  // lane = d
    const int warp = tid >> 5;               // 4 warps/block
    const int b0 = (blockIdx.x * 4 + warp) * 4;   // 4 rows per thread

    // x rows b0..b0+3 (uniform across warp -> broadcast LDG.128)
    const float4* xp = reinterpret_cast<const float4*>(x + b0 * S);
    float xs[4][8];
#pragma unroll
    for (int r = 0; r < 4; ++r) {
        const float4 a = xp[2 * r], bb = xp[2 * r + 1];
        xs[r][0] = a.x;  xs[r][1] = a.y;  xs[r][2] = a.z;  xs[r][3] = a.w;
        xs[r][4] = bb.x; xs[r][5] = bb.y; xs[r][6] = bb.z; xs[r][7] = bb.w;
    }

    // Packed sigmoids: PA[s] = (p_s row0, p_s row1), PB[s] = (row2, row3)
    u64 PA[8], PB[8];
#pragma unroll
    for (int s = 0; s < 8; ++s) {
        const float A = sA[s][d];
        const float C = sC[s][d];
        const float p0 = fast_sigmoid_prehalved(fmaf(A, xs[0][s], C));
        const float p1 = fast_sigmoid_prehalved(fmaf(A, xs[1][s], C));
        const float p2 = fast_sigmoid_prehalved(fmaf(A, xs[2][s], C));
        const float p3 = fast_sigmoid_prehalved(fmaf(A, xs[3][s], C));
        PA[s] = pack2(p0, p1);
        PB[s] = pack2(p2, p3);
    }

    // Horner inner (lo bits: bit0<->p7, bit1<->p6, bit2<->p5, bit3<->p4),
    // outer first level (p3) folded into the hi loop; uA/uB hold 8 partials.
    u64 uA[8], uB[8];
    u64 stashA, stashB;
    const ulonglong2* W2 = reinterpret_cast<const ulonglong2*>(sW2);
#pragma unroll
    for (int hi = 0; hi < 16; ++hi) {
        const ulonglong2 q0 = W2[hi * 8 + 0], q1 = W2[hi * 8 + 1];
        const ulonglong2 q2 = W2[hi * 8 + 2], q3 = W2[hi * 8 + 3];
        const ulonglong2 q4 = W2[hi * 8 + 4], q5 = W2[hi * 8 + 5];
        const ulonglong2 q6 = W2[hi * 8 + 6], q7 = W2[hi * 8 + 7];

#pragma unroll
        for (int pr = 0; pr < 2; ++pr) {
            const u64* P = pr ? PB : PA;
            // level A (p7): 8 fma2
            const u64 e0 = fma2(P[7], q0.y, q0.x);
            const u64 e1 = fma2(P[7], q1.y, q1.x);
            const u64 e2 = fma2(P[7], q2.y, q2.x);
            const u64 e3 = fma2(P[7], q3.y, q3.x);
            const u64 e4 = fma2(P[7], q4.y, q4.x);
            const u64 e5 = fma2(P[7], q5.y, q5.x);
            const u64 e6 = fma2(P[7], q6.y, q6.x);
            const u64 e7 = fma2(P[7], q7.y, q7.x);
            // level B (p6): 4
            const u64 f0 = fma2(P[6], e1, e0);
            const u64 f1 = fma2(P[6], e3, e2);
            const u64 f2 = fma2(P[6], e5, e4);
            const u64 f3 = fma2(P[6], e7, e6);
            // level C (p5): 2
            const u64 g0 = fma2(P[5], f1, f0);
            const u64 g1 = fma2(P[5], f3, f2);
            // level D (p4): 1
            const u64 inner = fma2(P[4], g1, g0);

            if ((hi & 1) == 0) {
                if (pr) stashB = inner; else stashA = inner;
            } else {
                if (pr) uB[hi >> 1] = fma2(P[3], inner, stashB);
                else    uA[hi >> 1] = fma2(P[3], inner, stashA);
            }
        }
    }

    const float bias = lin_b[0];
#pragma unroll
    for (int pr = 0; pr < 2; ++pr) {
        const u64* P = pr ? PB : PA;
        const u64* u = pr ? uB : uA;
        const u64 v0 = fma2(P[2], u[1], u[0]);
        const u64 v1 = fma2(P[2], u[3], u[2]);
        const u64 v2 = fma2(P[2], u[5], u[4]);
        const u64 v3 = fma2(P[2], u[7], u[6]);
        const u64 m0 = fma2(P[1], v1, v0);
        const u64 m1 = fma2(P[1], v3, v2);
        const u64 res = fma2(P[0], m1, m0);
        float rlo, rhi;
        unpack2(res, rlo, rhi);
        const int r0 = pr * 2;
        out[(b0 + r0) * D + d]     = rlo + bias;
        out[(b0 + r0 + 1) * D + d] = rhi + bias;
    }
}

extern "C" void kernel_launch(void* const* d_in, const int* in_sizes, int n_in,
                              void* d_out, int out_size) {
    const float* x     = (const float*)d_in[0];
    const float* k     = (const float*)d_in[1];
    const float* w     = (const float*)d_in[2];
    const float* q     = (const float*)d_in[3];
    // d_in[4] = mask (unused: fixed binary-expansion generation rule)
    const float* lin_w = (const float*)d_in[5];
    const float* lin_b = (const float*)d_in[6];
    float* out = (float*)d_out;

    // 128 threads = 4 warps; each warp: 4 rows/thread-pairs -> 16 rows/block
    dendrite_kernel<<<B / 16, 128>>>(x, k, w, q, lin_w, lin_b, out);
}